// round 1
// baseline (speedup 1.0000x reference)
#include <cuda_runtime.h>
#include <cstdint>

#define NPv 50000
#define NAv 50000
#define Dv  128

// ---------------- scratch (static device globals; no allocation) -------------
__device__ float g_agg1[(size_t)NPv * Dv];   // author->paper aggregate (in h-space)
__device__ float g_agg2[(size_t)NPv * Dv];   // paper->paper
__device__ float g_agg3[(size_t)NAv * Dv];   // author->author
__device__ float g_z1[(size_t)NPv * Dv];
__device__ float g_z2[(size_t)NPv * Dv];
__device__ float g_z3[(size_t)NAv * Dv];
__device__ float g_deg[6 * 50000];           // [0]=out_r1(NA) [1]=in_r1(NP) [2]=out_r2 [3]=in_r2 [4]=out_r3 [5]=in_r3
__device__ float g_stats[7 * 128];           // S1 S2 Q1 Q2 CX S3 Q3 (per column)
__device__ float g_wsum[2];                  // attention score sums for z1, z2
__device__ float g_beta[2];
__device__ float g_scale_p[128], g_shift_p[128];
__device__ float g_scale_a[128], g_shift_a[128];

// ---------------- zero scratch ----------------
__global__ void zero_kernel() {
    size_t i = (size_t)blockIdx.x * blockDim.x + threadIdx.x;
    size_t n1 = (size_t)NPv * Dv;
    if (i < n1) { g_agg1[i] = 0.f; g_agg2[i] = 0.f; g_agg3[i] = 0.f; }
    if (i < 6 * 50000) g_deg[i] = 0.f;
    if (i < 7 * 128) g_stats[i] = 0.f;
    if (i < 2) g_wsum[i] = 0.f;
}

// ---------------- degrees ----------------
__global__ void degree_kernel(const int* __restrict__ s1, const int* __restrict__ d1,
                              const int* __restrict__ s2, const int* __restrict__ d2,
                              const int* __restrict__ s3, const int* __restrict__ d3,
                              int nE) {
    int i = blockIdx.x * blockDim.x + threadIdx.x;
    if (i >= nE) return;
    atomicAdd(&g_deg[0 * 50000 + s1[i]], 1.0f);
    atomicAdd(&g_deg[1 * 50000 + d1[i]], 1.0f);
    atomicAdd(&g_deg[2 * 50000 + s2[i]], 1.0f);
    atomicAdd(&g_deg[3 * 50000 + d2[i]], 1.0f);
    atomicAdd(&g_deg[4 * 50000 + s3[i]], 1.0f);
    atomicAdd(&g_deg[5 * 50000 + d3[i]], 1.0f);
}

__global__ void rsqrt_deg_kernel(int n) {
    int i = blockIdx.x * blockDim.x + threadIdx.x;
    if (i < n) g_deg[i] = rsqrtf(fmaxf(g_deg[i], 1.0f));
}

// ---------------- scatter: agg[dst] += h[src] * rs_out[src] ----------------
// warp per edge, float4 per lane, vector red to L2
__global__ __launch_bounds__(256) void scatter_kernel(
    const float* __restrict__ H, const int* __restrict__ src, const int* __restrict__ dst,
    const float* __restrict__ rs_out, float* __restrict__ agg, int nE) {
    int gt = blockIdx.x * blockDim.x + threadIdx.x;
    int e = gt >> 5;
    int lane = gt & 31;
    if (e >= nE) return;
    int s = src[e];
    int d = dst[e];
    float sc = rs_out[s];
    float4 v = *((const float4*)(H + (size_t)s * Dv) + lane);
    v.x *= sc; v.y *= sc; v.z *= sc; v.w *= sc;
    float* p = agg + (size_t)d * Dv + lane * 4;
    asm volatile("red.global.add.v4.f32 [%0], {%1,%2,%3,%4};"
                 :: "l"(p), "f"(v.x), "f"(v.y), "f"(v.z), "f"(v.w) : "memory");
}

// ---------------- GEMM: C = (A @ W) * rs[row]   (M x 128 @ 128 x 128) --------
// 256 threads, 64 rows x 64 cols per block, thread tile 4x4
__global__ __launch_bounds__(256) void gemm_rowscale(
    const float* __restrict__ A, const float* __restrict__ W,
    const float* __restrict__ rs, float* __restrict__ C, int M) {
    __shared__ float Ws[128][64];
    const int tid = threadIdx.x;
    const int rowBase = blockIdx.x * 64;
    const int colBase = blockIdx.y * 64;

    for (int i = tid; i < 128 * 16; i += 256) {
        int k = i >> 4, c4 = (i & 15) << 2;
        *(float4*)&Ws[k][c4] = *(const float4*)(W + k * 128 + colBase + c4);
    }
    __syncthreads();

    const int tx = tid & 15, ty = tid >> 4;
    const int col = tx << 2;

    int rr0 = min(rowBase + ty * 4 + 0, M - 1);
    int rr1 = min(rowBase + ty * 4 + 1, M - 1);
    int rr2 = min(rowBase + ty * 4 + 2, M - 1);
    int rr3 = min(rowBase + ty * 4 + 3, M - 1);
    const float4* A0 = (const float4*)(A + (size_t)rr0 * 128);
    const float4* A1 = (const float4*)(A + (size_t)rr1 * 128);
    const float4* A2 = (const float4*)(A + (size_t)rr2 * 128);
    const float4* A3 = (const float4*)(A + (size_t)rr3 * 128);

    float acc[4][4] = {};
#pragma unroll 4
    for (int k4 = 0; k4 < 32; k4++) {
        float4 a0 = A0[k4], a1 = A1[k4], a2 = A2[k4], a3 = A3[k4];
#pragma unroll
        for (int kk = 0; kk < 4; kk++) {
            float4 w = *(const float4*)&Ws[k4 * 4 + kk][col];
            float v0 = (&a0.x)[kk], v1 = (&a1.x)[kk], v2 = (&a2.x)[kk], v3 = (&a3.x)[kk];
            acc[0][0] += v0 * w.x; acc[0][1] += v0 * w.y; acc[0][2] += v0 * w.z; acc[0][3] += v0 * w.w;
            acc[1][0] += v1 * w.x; acc[1][1] += v1 * w.y; acc[1][2] += v1 * w.z; acc[1][3] += v1 * w.w;
            acc[2][0] += v2 * w.x; acc[2][1] += v2 * w.y; acc[2][2] += v2 * w.z; acc[2][3] += v2 * w.w;
            acc[3][0] += v3 * w.x; acc[3][1] += v3 * w.y; acc[3][2] += v3 * w.z; acc[3][3] += v3 * w.w;
        }
    }
#pragma unroll
    for (int r = 0; r < 4; r++) {
        int row = rowBase + ty * 4 + r;
        if (row < M) {
            float s = rs[row];
            float4 o = make_float4(acc[r][0] * s, acc[r][1] * s, acc[r][2] * s, acc[r][3] * s);
            *(float4*)(C + (size_t)row * 128 + colBase + col) = o;
        }
    }
}

// ---------------- attention score: wsum += sum_rows tanh(Z@attW + b) . q ----
__global__ __launch_bounds__(256) void att_score_kernel(
    const float* __restrict__ Z, const float* __restrict__ attW,
    const float* __restrict__ attb, const float* __restrict__ attq,
    float* __restrict__ wsum, int M) {
    __shared__ float Ws[128][64];
    __shared__ float ssum;
    const int tid = threadIdx.x;
    const int rowBase = blockIdx.x * 64;
    const int colBase = blockIdx.y * 64;
    if (tid == 0) ssum = 0.f;

    for (int i = tid; i < 128 * 16; i += 256) {
        int k = i >> 4, c4 = (i & 15) << 2;
        *(float4*)&Ws[k][c4] = *(const float4*)(attW + k * 128 + colBase + c4);
    }
    __syncthreads();

    const int tx = tid & 15, ty = tid >> 4;
    const int col = tx << 2;

    int rr0 = min(rowBase + ty * 4 + 0, M - 1);
    int rr1 = min(rowBase + ty * 4 + 1, M - 1);
    int rr2 = min(rowBase + ty * 4 + 2, M - 1);
    int rr3 = min(rowBase + ty * 4 + 3, M - 1);
    const float4* A0 = (const float4*)(Z + (size_t)rr0 * 128);
    const float4* A1 = (const float4*)(Z + (size_t)rr1 * 128);
    const float4* A2 = (const float4*)(Z + (size_t)rr2 * 128);
    const float4* A3 = (const float4*)(Z + (size_t)rr3 * 128);

    float acc[4][4] = {};
#pragma unroll 4
    for (int k4 = 0; k4 < 32; k4++) {
        float4 a0 = A0[k4], a1 = A1[k4], a2 = A2[k4], a3 = A3[k4];
#pragma unroll
        for (int kk = 0; kk < 4; kk++) {
            float4 w = *(const float4*)&Ws[k4 * 4 + kk][col];
            float v0 = (&a0.x)[kk], v1 = (&a1.x)[kk], v2 = (&a2.x)[kk], v3 = (&a3.x)[kk];
            acc[0][0] += v0 * w.x; acc[0][1] += v0 * w.y; acc[0][2] += v0 * w.z; acc[0][3] += v0 * w.w;
            acc[1][0] += v1 * w.x; acc[1][1] += v1 * w.y; acc[1][2] += v1 * w.z; acc[1][3] += v1 * w.w;
            acc[2][0] += v2 * w.x; acc[2][1] += v2 * w.y; acc[2][2] += v2 * w.z; acc[2][3] += v2 * w.w;
            acc[3][0] += v3 * w.x; acc[3][1] += v3 * w.y; acc[3][2] += v3 * w.z; acc[3][3] += v3 * w.w;
        }
    }

    float bq_b[4], bq_q[4];
#pragma unroll
    for (int j = 0; j < 4; j++) {
        bq_b[j] = attb[colBase + col + j];
        bq_q[j] = attq[colBase + col + j];
    }
    float p = 0.f;
#pragma unroll
    for (int r = 0; r < 4; r++) {
        int row = rowBase + ty * 4 + r;
        if (row < M) {
#pragma unroll
            for (int j = 0; j < 4; j++)
                p += tanhf(acc[r][j] + bq_b[j]) * bq_q[j];
        }
    }
    // reduce across the 16 tx lanes of each half-warp
    p += __shfl_down_sync(0xffffffffu, p, 8, 16);
    p += __shfl_down_sync(0xffffffffu, p, 4, 16);
    p += __shfl_down_sync(0xffffffffu, p, 2, 16);
    p += __shfl_down_sync(0xffffffffu, p, 1, 16);
    if (tx == 0) atomicAdd(&ssum, p);
    __syncthreads();
    if (tid == 0) atomicAdd(wsum, ssum);
}

// ---------------- column moments ----------------
__global__ __launch_bounds__(128) void stats_paper_kernel(
    const float* __restrict__ z1, const float* __restrict__ z2, int M) {
    int c = threadIdx.x;
    int r0 = blockIdx.x * 256;
    int r1 = min(r0 + 256, M);
    float s1 = 0.f, s2 = 0.f, q1 = 0.f, q2 = 0.f, cx = 0.f;
    for (int r = r0; r < r1; r++) {
        float v1 = z1[(size_t)r * 128 + c];
        float v2 = z2[(size_t)r * 128 + c];
        s1 += v1; s2 += v2; q1 += v1 * v1; q2 += v2 * v2; cx += v1 * v2;
    }
    atomicAdd(&g_stats[0 * 128 + c], s1);
    atomicAdd(&g_stats[1 * 128 + c], s2);
    atomicAdd(&g_stats[2 * 128 + c], q1);
    atomicAdd(&g_stats[3 * 128 + c], q2);
    atomicAdd(&g_stats[4 * 128 + c], cx);
}

__global__ __launch_bounds__(128) void stats_author_kernel(const float* __restrict__ z3, int M) {
    int c = threadIdx.x;
    int r0 = blockIdx.x * 256;
    int r1 = min(r0 + 256, M);
    float s3 = 0.f, q3 = 0.f;
    for (int r = r0; r < r1; r++) {
        float v = z3[(size_t)r * 128 + c];
        s3 += v; q3 += v * v;
    }
    atomicAdd(&g_stats[5 * 128 + c], s3);
    atomicAdd(&g_stats[6 * 128 + c], q3);
}

// ---------------- finalize: beta softmax + BN affine params ----------------
__global__ void finalize_kernel(const float* __restrict__ gamma, const float* __restrict__ betaBN,
                                int MP, int MA) {
    int j = threadIdx.x;  // 128 threads
    float w1 = g_wsum[0] / (float)MP;
    float w2 = g_wsum[1] / (float)MP;
    float m = fmaxf(w1, w2);
    float e1 = expf(w1 - m), e2 = expf(w2 - m);
    float b1 = e1 / (e1 + e2), b2 = e2 / (e1 + e2);
    if (j == 0) { g_beta[0] = b1; g_beta[1] = b2; }

    float S1 = g_stats[0 * 128 + j], S2 = g_stats[1 * 128 + j];
    float Q1 = g_stats[2 * 128 + j], Q2 = g_stats[3 * 128 + j];
    float CX = g_stats[4 * 128 + j];
    float S3 = g_stats[5 * 128 + j], Q3 = g_stats[6 * 128 + j];

    float invMP = 1.0f / (float)MP;
    float mu = (b1 * S1 + b2 * S2) * invMP;
    float ex2 = (b1 * b1 * Q1 + 2.f * b1 * b2 * CX + b2 * b2 * Q2) * invMP;
    float var = ex2 - mu * mu;
    float sc = gamma[j] * rsqrtf(var + 1e-5f);
    g_scale_p[j] = sc;
    g_shift_p[j] = betaBN[j] - mu * sc;

    float invMA = 1.0f / (float)MA;
    float mua = S3 * invMA;
    float vara = Q3 * invMA - mua * mua;
    float sca = gamma[j] * rsqrtf(vara + 1e-5f);
    g_scale_a[j] = sca;
    g_shift_a[j] = betaBN[j] - mua * sca;
}

// ---------------- combine + BN + row L2 normalize ----------------
__global__ __launch_bounds__(256) void out_paper_kernel(
    const float* __restrict__ z1, const float* __restrict__ z2,
    float* __restrict__ out, int M) {
    int gt = blockIdx.x * blockDim.x + threadIdx.x;
    int row = gt >> 5, lane = gt & 31;
    if (row >= M) return;
    float b1 = g_beta[0], b2 = g_beta[1];
    float4 v1 = *((const float4*)(z1 + (size_t)row * 128) + lane);
    float4 v2 = *((const float4*)(z2 + (size_t)row * 128) + lane);
    float4 sc = *(const float4*)&g_scale_p[lane * 4];
    float4 sh = *(const float4*)&g_shift_p[lane * 4];
    float4 y;
    y.x = (b1 * v1.x + b2 * v2.x) * sc.x + sh.x;
    y.y = (b1 * v1.y + b2 * v2.y) * sc.y + sh.y;
    y.z = (b1 * v1.z + b2 * v2.z) * sc.z + sh.z;
    y.w = (b1 * v1.w + b2 * v2.w) * sc.w + sh.w;
    float ss = y.x * y.x + y.y * y.y + y.z * y.z + y.w * y.w;
#pragma unroll
    for (int o = 16; o > 0; o >>= 1) ss += __shfl_xor_sync(0xffffffffu, ss, o);
    float inv = rsqrtf(ss + 1e-12f);
    float4 o4 = make_float4(y.x * inv, y.y * inv, y.z * inv, y.w * inv);
    *((float4*)(out + (size_t)row * 128) + lane) = o4;
}

__global__ __launch_bounds__(256) void out_author_kernel(
    const float* __restrict__ z3, float* __restrict__ out, int M) {
    int gt = blockIdx.x * blockDim.x + threadIdx.x;
    int row = gt >> 5, lane = gt & 31;
    if (row >= M) return;
    float4 v = *((const float4*)(z3 + (size_t)row * 128) + lane);
    float4 sc = *(const float4*)&g_scale_a[lane * 4];
    float4 sh = *(const float4*)&g_shift_a[lane * 4];
    float4 y;
    y.x = v.x * sc.x + sh.x;
    y.y = v.y * sc.y + sh.y;
    y.z = v.z * sc.z + sh.z;
    y.w = v.w * sc.w + sh.w;
    float ss = y.x * y.x + y.y * y.y + y.z * y.z + y.w * y.w;
#pragma unroll
    for (int o = 16; o > 0; o >>= 1) ss += __shfl_xor_sync(0xffffffffu, ss, o);
    float inv = rsqrtf(ss + 1e-12f);
    float4 o4 = make_float4(y.x * inv, y.y * inv, y.z * inv, y.w * inv);
    *((float4*)(out + (size_t)row * 128) + lane) = o4;
}

// ---------------- launch ----------------
extern "C" void kernel_launch(void* const* d_in, const int* in_sizes, int n_in,
                              void* d_out, int out_size) {
    const float* h_paper  = (const float*)d_in[0];
    const float* h_author = (const float*)d_in[1];
    const float* W1   = (const float*)d_in[2];
    const float* W2   = (const float*)d_in[3];
    const float* W3   = (const float*)d_in[4];
    const float* attW = (const float*)d_in[5];
    const float* attb = (const float*)d_in[6];
    const float* attq = (const float*)d_in[7];
    const float* gamma  = (const float*)d_in[8];
    const float* betaBN = (const float*)d_in[9];
    const int* s1 = (const int*)d_in[10];
    const int* d1 = (const int*)d_in[11];
    const int* s2 = (const int*)d_in[12];
    const int* d2 = (const int*)d_in[13];
    const int* s3 = (const int*)d_in[14];
    const int* d3 = (const int*)d_in[15];
    float* out = (float*)d_out;

    const int MP = in_sizes[0] / Dv;   // 50000 papers
    const int MA = in_sizes[1] / Dv;   // 50000 authors
    const int E  = in_sizes[10];       // 800000

    float *agg1, *agg2, *agg3, *z1, *z2, *z3, *deg, *wsum;
    cudaGetSymbolAddress((void**)&agg1, g_agg1);
    cudaGetSymbolAddress((void**)&agg2, g_agg2);
    cudaGetSymbolAddress((void**)&agg3, g_agg3);
    cudaGetSymbolAddress((void**)&z1, g_z1);
    cudaGetSymbolAddress((void**)&z2, g_z2);
    cudaGetSymbolAddress((void**)&z3, g_z3);
    cudaGetSymbolAddress((void**)&deg, g_deg);
    cudaGetSymbolAddress((void**)&wsum, g_wsum);

    // 1. zero scratch
    {
        size_t n = (size_t)MP * Dv;
        int blocks = (int)((n + 255) / 256);
        zero_kernel<<<blocks, 256>>>();
    }
    // 2. degrees
    degree_kernel<<<(E + 255) / 256, 256>>>(s1, d1, s2, d2, s3, d3, E);
    rsqrt_deg_kernel<<<(6 * 50000 + 255) / 256, 256>>>(6 * 50000);

    // 3. scatter (aggregate in input space; GEMM after)
    {
        int blocks = (E * 32 + 255) / 256;
        scatter_kernel<<<blocks, 256>>>(h_author, s1, d1, deg + 0 * 50000, agg1, E);
        scatter_kernel<<<blocks, 256>>>(h_paper,  s2, d2, deg + 2 * 50000, agg2, E);
        scatter_kernel<<<blocks, 256>>>(h_author, s3, d3, deg + 4 * 50000, agg3, E);
    }

    // 4. conv GEMMs: z = (agg @ W) * rsqrt(deg_in)
    {
        dim3 gP((MP + 63) / 64, 2), gA((MA + 63) / 64, 2);
        gemm_rowscale<<<gP, 256>>>(agg1, W1, deg + 1 * 50000, z1, MP);
        gemm_rowscale<<<gP, 256>>>(agg2, W2, deg + 3 * 50000, z2, MP);
        gemm_rowscale<<<gA, 256>>>(agg3, W3, deg + 5 * 50000, z3, MA);
    }

    // 5. attention scores (papers only; author beta == 1 identically)
    {
        dim3 gP((MP + 63) / 64, 2);
        att_score_kernel<<<gP, 256>>>(z1, attW, attb, attq, wsum + 0, MP);
        att_score_kernel<<<gP, 256>>>(z2, attW, attb, attq, wsum + 1, MP);
    }

    // 6. column moments for BN
    stats_paper_kernel<<<(MP + 255) / 256, 128>>>(z1, z2, MP);
    stats_author_kernel<<<(MA + 255) / 256, 128>>>(z3, MA);

    // 7. beta + BN affine params
    finalize_kernel<<<1, 128>>>(gamma, betaBN, MP, MA);

    // 8. combine + BN + L2 normalize
    out_paper_kernel<<<(MP * 32 + 255) / 256, 256>>>(z1, z2, out, MP);
    out_author_kernel<<<(MA * 32 + 255) / 256, 256>>>(z3, out + (size_t)MP * Dv, MA);
}

// round 2
// speedup vs baseline: 1.0871x; 1.0871x over previous
#include <cuda_runtime.h>
#include <cstdint>

#define NPv 50000
#define NAv 50000
#define Dv  128

// ---------------- scratch (static device globals; no allocation) -------------
__device__ float g_agg1[(size_t)NPv * Dv];
__device__ float g_agg2[(size_t)NPv * Dv];
__device__ float g_agg3[(size_t)NAv * Dv];
__device__ float g_z1[(size_t)NPv * Dv];
__device__ float g_z2[(size_t)NPv * Dv];
__device__ float g_z3[(size_t)NAv * Dv];
__device__ float g_deg[6 * 50000];
__device__ float g_stats[7 * 128];
__device__ float g_wsum[2];
__device__ float g_beta[2];
__device__ float g_scale_p[128], g_shift_p[128];
__device__ float g_scale_a[128], g_shift_a[128];

// ---------------- f32x2 helpers ----------------
__device__ __forceinline__ uint64_t pack2(float x, float y) {
    uint64_t r;
    asm("mov.b64 %0, {%1, %2};" : "=l"(r) : "f"(x), "f"(y));
    return r;
}
__device__ __forceinline__ void unpack2(uint64_t v, float& x, float& y) {
    asm("mov.b64 {%0, %1}, %2;" : "=f"(x), "=f"(y) : "l"(v));
}
__device__ __forceinline__ uint64_t ffma2(uint64_t a, uint64_t b, uint64_t c) {
    uint64_t d;
    asm("fma.rn.f32x2 %0, %1, %2, %3;" : "=l"(d) : "l"(a), "l"(b), "l"(c));
    return d;
}

// ---------------- zero scratch ----------------
__global__ void zero_kernel() {
    size_t i = (size_t)blockIdx.x * blockDim.x + threadIdx.x;
    size_t n1 = (size_t)NPv * Dv;
    if (i < n1) { g_agg1[i] = 0.f; g_agg2[i] = 0.f; g_agg3[i] = 0.f; }
    if (i < 6 * 50000) g_deg[i] = 0.f;
    if (i < 7 * 128) g_stats[i] = 0.f;
    if (i < 2) g_wsum[i] = 0.f;
}

// ---------------- degrees ----------------
__global__ void degree_kernel(const int* __restrict__ s1, const int* __restrict__ d1,
                              const int* __restrict__ s2, const int* __restrict__ d2,
                              const int* __restrict__ s3, const int* __restrict__ d3,
                              int nE) {
    int i = blockIdx.x * blockDim.x + threadIdx.x;
    if (i >= nE) return;
    atomicAdd(&g_deg[0 * 50000 + s1[i]], 1.0f);
    atomicAdd(&g_deg[1 * 50000 + d1[i]], 1.0f);
    atomicAdd(&g_deg[2 * 50000 + s2[i]], 1.0f);
    atomicAdd(&g_deg[3 * 50000 + d2[i]], 1.0f);
    atomicAdd(&g_deg[4 * 50000 + s3[i]], 1.0f);
    atomicAdd(&g_deg[5 * 50000 + d3[i]], 1.0f);
}

__global__ void rsqrt_deg_kernel(int n) {
    int i = blockIdx.x * blockDim.x + threadIdx.x;
    if (i < n) g_deg[i] = rsqrtf(fmaxf(g_deg[i], 1.0f));
}

// ---------------- scatter: 4 edges per warp for MLP ----------------
__global__ __launch_bounds__(256) void scatter_kernel(
    const float* __restrict__ H, const int* __restrict__ src, const int* __restrict__ dst,
    const float* __restrict__ rs_out, float* __restrict__ agg, int nE) {
    int warp = (blockIdx.x * blockDim.x + threadIdx.x) >> 5;
    int lane = threadIdx.x & 31;
    int e0 = warp << 2;
    if (e0 >= nE) return;

    int s[4], d[4];
#pragma unroll
    for (int i = 0; i < 4; i++) {
        int e = min(e0 + i, nE - 1);
        s[i] = __ldg(src + e);
        d[i] = __ldg(dst + e);
    }
    float sc[4];
#pragma unroll
    for (int i = 0; i < 4; i++) sc[i] = __ldg(rs_out + s[i]);
    float4 v[4];
#pragma unroll
    for (int i = 0; i < 4; i++)
        v[i] = *((const float4*)(H + (size_t)s[i] * Dv) + lane);

    int n = min(4, nE - e0);
#pragma unroll
    for (int i = 0; i < 4; i++) {
        if (i < n) {
            float4 u = v[i];
            float c = sc[i];
            u.x *= c; u.y *= c; u.z *= c; u.w *= c;
            float* p = agg + (size_t)d[i] * Dv + lane * 4;
            asm volatile("red.global.add.v4.f32 [%0], {%1,%2,%3,%4};"
                         :: "l"(p), "f"(u.x), "f"(u.y), "f"(u.z), "f"(u.w) : "memory");
        }
    }
}

// ---------------- GEMM (f32x2): C = (A @ W) * rs[row] ------------------------
// 256 threads, 64 rows x 64 cols per block, thread tile 4 rows x 4 cols (2 f32x2 pairs)
__global__ __launch_bounds__(256) void gemm_rowscale(
    const float* __restrict__ A, const float* __restrict__ W,
    const float* __restrict__ rs, float* __restrict__ C, int M) {
    __shared__ float Ws[128][64];
    const int tid = threadIdx.x;
    const int rowBase = blockIdx.x * 64;
    const int colBase = blockIdx.y * 64;

    for (int i = tid; i < 128 * 16; i += 256) {
        int k = i >> 4, c4 = (i & 15) << 2;
        *(float4*)&Ws[k][c4] = *(const float4*)(W + k * 128 + colBase + c4);
    }
    __syncthreads();

    const int tx = tid & 15, ty = tid >> 4;
    const int col = tx << 2;

    int rr0 = min(rowBase + ty * 4 + 0, M - 1);
    int rr1 = min(rowBase + ty * 4 + 1, M - 1);
    int rr2 = min(rowBase + ty * 4 + 2, M - 1);
    int rr3 = min(rowBase + ty * 4 + 3, M - 1);
    const float4* A0 = (const float4*)(A + (size_t)rr0 * 128);
    const float4* A1 = (const float4*)(A + (size_t)rr1 * 128);
    const float4* A2 = (const float4*)(A + (size_t)rr2 * 128);
    const float4* A3 = (const float4*)(A + (size_t)rr3 * 128);

    uint64_t acc[4][2];
#pragma unroll
    for (int r = 0; r < 4; r++) { acc[r][0] = pack2(0.f, 0.f); acc[r][1] = pack2(0.f, 0.f); }

#pragma unroll 4
    for (int k4 = 0; k4 < 32; k4++) {
        float4 a0 = A0[k4], a1 = A1[k4], a2 = A2[k4], a3 = A3[k4];
#pragma unroll
        for (int kk = 0; kk < 4; kk++) {
            float4 w = *(const float4*)&Ws[k4 * 4 + kk][col];
            uint64_t wp0 = pack2(w.x, w.y);
            uint64_t wp1 = pack2(w.z, w.w);
            float v0 = (&a0.x)[kk], v1 = (&a1.x)[kk], v2 = (&a2.x)[kk], v3 = (&a3.x)[kk];
            uint64_t vv0 = pack2(v0, v0), vv1 = pack2(v1, v1);
            uint64_t vv2 = pack2(v2, v2), vv3 = pack2(v3, v3);
            acc[0][0] = ffma2(vv0, wp0, acc[0][0]); acc[0][1] = ffma2(vv0, wp1, acc[0][1]);
            acc[1][0] = ffma2(vv1, wp0, acc[1][0]); acc[1][1] = ffma2(vv1, wp1, acc[1][1]);
            acc[2][0] = ffma2(vv2, wp0, acc[2][0]); acc[2][1] = ffma2(vv2, wp1, acc[2][1]);
            acc[3][0] = ffma2(vv3, wp0, acc[3][0]); acc[3][1] = ffma2(vv3, wp1, acc[3][1]);
        }
    }
#pragma unroll
    for (int r = 0; r < 4; r++) {
        int row = rowBase + ty * 4 + r;
        if (row < M) {
            float s = rs[row];
            float4 o;
            unpack2(acc[r][0], o.x, o.y);
            unpack2(acc[r][1], o.z, o.w);
            o.x *= s; o.y *= s; o.z *= s; o.w *= s;
            *(float4*)(C + (size_t)row * 128 + colBase + col) = o;
        }
    }
}

// ---------------- attention score (f32x2 GEMM + tanh dot) --------------------
__global__ __launch_bounds__(256) void att_score_kernel(
    const float* __restrict__ Z, const float* __restrict__ attW,
    const float* __restrict__ attb, const float* __restrict__ attq,
    float* __restrict__ wsum, int M) {
    __shared__ float Ws[128][64];
    __shared__ float ssum;
    const int tid = threadIdx.x;
    const int rowBase = blockIdx.x * 64;
    const int colBase = blockIdx.y * 64;
    if (tid == 0) ssum = 0.f;

    for (int i = tid; i < 128 * 16; i += 256) {
        int k = i >> 4, c4 = (i & 15) << 2;
        *(float4*)&Ws[k][c4] = *(const float4*)(attW + k * 128 + colBase + c4);
    }
    __syncthreads();

    const int tx = tid & 15, ty = tid >> 4;
    const int col = tx << 2;

    int rr0 = min(rowBase + ty * 4 + 0, M - 1);
    int rr1 = min(rowBase + ty * 4 + 1, M - 1);
    int rr2 = min(rowBase + ty * 4 + 2, M - 1);
    int rr3 = min(rowBase + ty * 4 + 3, M - 1);
    const float4* A0 = (const float4*)(Z + (size_t)rr0 * 128);
    const float4* A1 = (const float4*)(Z + (size_t)rr1 * 128);
    const float4* A2 = (const float4*)(Z + (size_t)rr2 * 128);
    const float4* A3 = (const float4*)(Z + (size_t)rr3 * 128);

    uint64_t acc[4][2];
#pragma unroll
    for (int r = 0; r < 4; r++) { acc[r][0] = pack2(0.f, 0.f); acc[r][1] = pack2(0.f, 0.f); }

#pragma unroll 4
    for (int k4 = 0; k4 < 32; k4++) {
        float4 a0 = A0[k4], a1 = A1[k4], a2 = A2[k4], a3 = A3[k4];
#pragma unroll
        for (int kk = 0; kk < 4; kk++) {
            float4 w = *(const float4*)&Ws[k4 * 4 + kk][col];
            uint64_t wp0 = pack2(w.x, w.y);
            uint64_t wp1 = pack2(w.z, w.w);
            float v0 = (&a0.x)[kk], v1 = (&a1.x)[kk], v2 = (&a2.x)[kk], v3 = (&a3.x)[kk];
            uint64_t vv0 = pack2(v0, v0), vv1 = pack2(v1, v1);
            uint64_t vv2 = pack2(v2, v2), vv3 = pack2(v3, v3);
            acc[0][0] = ffma2(vv0, wp0, acc[0][0]); acc[0][1] = ffma2(vv0, wp1, acc[0][1]);
            acc[1][0] = ffma2(vv1, wp0, acc[1][0]); acc[1][1] = ffma2(vv1, wp1, acc[1][1]);
            acc[2][0] = ffma2(vv2, wp0, acc[2][0]); acc[2][1] = ffma2(vv2, wp1, acc[2][1]);
            acc[3][0] = ffma2(vv3, wp0, acc[3][0]); acc[3][1] = ffma2(vv3, wp1, acc[3][1]);
        }
    }

    float bq_b[4], bq_q[4];
#pragma unroll
    for (int j = 0; j < 4; j++) {
        bq_b[j] = attb[colBase + col + j];
        bq_q[j] = attq[colBase + col + j];
    }
    float p = 0.f;
#pragma unroll
    for (int r = 0; r < 4; r++) {
        int row = rowBase + ty * 4 + r;
        if (row < M) {
            float av[4];
            unpack2(acc[r][0], av[0], av[1]);
            unpack2(acc[r][1], av[2], av[3]);
#pragma unroll
            for (int j = 0; j < 4; j++)
                p += tanhf(av[j] + bq_b[j]) * bq_q[j];
        }
    }
    p += __shfl_down_sync(0xffffffffu, p, 8, 16);
    p += __shfl_down_sync(0xffffffffu, p, 4, 16);
    p += __shfl_down_sync(0xffffffffu, p, 2, 16);
    p += __shfl_down_sync(0xffffffffu, p, 1, 16);
    if (tx == 0) atomicAdd(&ssum, p);
    __syncthreads();
    if (tid == 0) atomicAdd(wsum, ssum);
}

// ---------------- column moments ----------------
__global__ __launch_bounds__(128) void stats_paper_kernel(
    const float* __restrict__ z1, const float* __restrict__ z2, int M) {
    int c = threadIdx.x;
    int r0 = blockIdx.x * 256;
    int r1 = min(r0 + 256, M);
    float s1 = 0.f, s2 = 0.f, q1 = 0.f, q2 = 0.f, cx = 0.f;
    for (int r = r0; r < r1; r++) {
        float v1 = z1[(size_t)r * 128 + c];
        float v2 = z2[(size_t)r * 128 + c];
        s1 += v1; s2 += v2; q1 += v1 * v1; q2 += v2 * v2; cx += v1 * v2;
    }
    atomicAdd(&g_stats[0 * 128 + c], s1);
    atomicAdd(&g_stats[1 * 128 + c], s2);
    atomicAdd(&g_stats[2 * 128 + c], q1);
    atomicAdd(&g_stats[3 * 128 + c], q2);
    atomicAdd(&g_stats[4 * 128 + c], cx);
}

__global__ __launch_bounds__(128) void stats_author_kernel(const float* __restrict__ z3, int M) {
    int c = threadIdx.x;
    int r0 = blockIdx.x * 256;
    int r1 = min(r0 + 256, M);
    float s3 = 0.f, q3 = 0.f;
    for (int r = r0; r < r1; r++) {
        float v = z3[(size_t)r * 128 + c];
        s3 += v; q3 += v * v;
    }
    atomicAdd(&g_stats[5 * 128 + c], s3);
    atomicAdd(&g_stats[6 * 128 + c], q3);
}

// ---------------- finalize: beta softmax + BN affine params ----------------
__global__ void finalize_kernel(const float* __restrict__ gamma, const float* __restrict__ betaBN,
                                int MP, int MA) {
    int j = threadIdx.x;
    float w1 = g_wsum[0] / (float)MP;
    float w2 = g_wsum[1] / (float)MP;
    float m = fmaxf(w1, w2);
    float e1 = expf(w1 - m), e2 = expf(w2 - m);
    float b1 = e1 / (e1 + e2), b2 = e2 / (e1 + e2);
    if (j == 0) { g_beta[0] = b1; g_beta[1] = b2; }

    float S1 = g_stats[0 * 128 + j], S2 = g_stats[1 * 128 + j];
    float Q1 = g_stats[2 * 128 + j], Q2 = g_stats[3 * 128 + j];
    float CX = g_stats[4 * 128 + j];
    float S3 = g_stats[5 * 128 + j], Q3 = g_stats[6 * 128 + j];

    float invMP = 1.0f / (float)MP;
    float mu = (b1 * S1 + b2 * S2) * invMP;
    float ex2 = (b1 * b1 * Q1 + 2.f * b1 * b2 * CX + b2 * b2 * Q2) * invMP;
    float var = ex2 - mu * mu;
    float sc = gamma[j] * rsqrtf(var + 1e-5f);
    g_scale_p[j] = sc;
    g_shift_p[j] = betaBN[j] - mu * sc;

    float invMA = 1.0f / (float)MA;
    float mua = S3 * invMA;
    float vara = Q3 * invMA - mua * mua;
    float sca = gamma[j] * rsqrtf(vara + 1e-5f);
    g_scale_a[j] = sca;
    g_shift_a[j] = betaBN[j] - mua * sca;
}

// ---------------- combine + BN + row L2 normalize ----------------
__global__ __launch_bounds__(256) void out_paper_kernel(
    const float* __restrict__ z1, const float* __restrict__ z2,
    float* __restrict__ out, int M) {
    int gt = blockIdx.x * blockDim.x + threadIdx.x;
    int row = gt >> 5, lane = gt & 31;
    if (row >= M) return;
    float b1 = g_beta[0], b2 = g_beta[1];
    float4 v1 = *((const float4*)(z1 + (size_t)row * 128) + lane);
    float4 v2 = *((const float4*)(z2 + (size_t)row * 128) + lane);
    float4 sc = *(const float4*)&g_scale_p[lane * 4];
    float4 sh = *(const float4*)&g_shift_p[lane * 4];
    float4 y;
    y.x = (b1 * v1.x + b2 * v2.x) * sc.x + sh.x;
    y.y = (b1 * v1.y + b2 * v2.y) * sc.y + sh.y;
    y.z = (b1 * v1.z + b2 * v2.z) * sc.z + sh.z;
    y.w = (b1 * v1.w + b2 * v2.w) * sc.w + sh.w;
    float ss = y.x * y.x + y.y * y.y + y.z * y.z + y.w * y.w;
#pragma unroll
    for (int o = 16; o > 0; o >>= 1) ss += __shfl_xor_sync(0xffffffffu, ss, o);
    float inv = rsqrtf(ss + 1e-12f);
    float4 o4 = make_float4(y.x * inv, y.y * inv, y.z * inv, y.w * inv);
    *((float4*)(out + (size_t)row * 128) + lane) = o4;
}

__global__ __launch_bounds__(256) void out_author_kernel(
    const float* __restrict__ z3, float* __restrict__ out, int M) {
    int gt = blockIdx.x * blockDim.x + threadIdx.x;
    int row = gt >> 5, lane = gt & 31;
    if (row >= M) return;
    float4 v = *((const float4*)(z3 + (size_t)row * 128) + lane);
    float4 sc = *(const float4*)&g_scale_a[lane * 4];
    float4 sh = *(const float4*)&g_shift_a[lane * 4];
    float4 y;
    y.x = v.x * sc.x + sh.x;
    y.y = v.y * sc.y + sh.y;
    y.z = v.z * sc.z + sh.z;
    y.w = v.w * sc.w + sh.w;
    float ss = y.x * y.x + y.y * y.y + y.z * y.z + y.w * y.w;
#pragma unroll
    for (int o = 16; o > 0; o >>= 1) ss += __shfl_xor_sync(0xffffffffu, ss, o);
    float inv = rsqrtf(ss + 1e-12f);
    float4 o4 = make_float4(y.x * inv, y.y * inv, y.z * inv, y.w * inv);
    *((float4*)(out + (size_t)row * 128) + lane) = o4;
}

// ---------------- launch ----------------
extern "C" void kernel_launch(void* const* d_in, const int* in_sizes, int n_in,
                              void* d_out, int out_size) {
    const float* h_paper  = (const float*)d_in[0];
    const float* h_author = (const float*)d_in[1];
    const float* W1   = (const float*)d_in[2];
    const float* W2   = (const float*)d_in[3];
    const float* W3   = (const float*)d_in[4];
    const float* attW = (const float*)d_in[5];
    const float* attb = (const float*)d_in[6];
    const float* attq = (const float*)d_in[7];
    const float* gamma  = (const float*)d_in[8];
    const float* betaBN = (const float*)d_in[9];
    const int* s1 = (const int*)d_in[10];
    const int* d1 = (const int*)d_in[11];
    const int* s2 = (const int*)d_in[12];
    const int* d2 = (const int*)d_in[13];
    const int* s3 = (const int*)d_in[14];
    const int* d3 = (const int*)d_in[15];
    float* out = (float*)d_out;

    const int MP = in_sizes[0] / Dv;
    const int MA = in_sizes[1] / Dv;
    const int E  = in_sizes[10];

    float *agg1, *agg2, *agg3, *z1, *z2, *z3, *deg, *wsum;
    cudaGetSymbolAddress((void**)&agg1, g_agg1);
    cudaGetSymbolAddress((void**)&agg2, g_agg2);
    cudaGetSymbolAddress((void**)&agg3, g_agg3);
    cudaGetSymbolAddress((void**)&z1, g_z1);
    cudaGetSymbolAddress((void**)&z2, g_z2);
    cudaGetSymbolAddress((void**)&z3, g_z3);
    cudaGetSymbolAddress((void**)&deg, g_deg);
    cudaGetSymbolAddress((void**)&wsum, g_wsum);

    {
        size_t n = (size_t)MP * Dv;
        int blocks = (int)((n + 255) / 256);
        zero_kernel<<<blocks, 256>>>();
    }
    degree_kernel<<<(E + 255) / 256, 256>>>(s1, d1, s2, d2, s3, d3, E);
    rsqrt_deg_kernel<<<(6 * 50000 + 255) / 256, 256>>>(6 * 50000);

    {
        int warps = (E + 3) / 4;
        int blocks = (warps * 32 + 255) / 256;
        scatter_kernel<<<blocks, 256>>>(h_author, s1, d1, deg + 0 * 50000, agg1, E);
        scatter_kernel<<<blocks, 256>>>(h_paper,  s2, d2, deg + 2 * 50000, agg2, E);
        scatter_kernel<<<blocks, 256>>>(h_author, s3, d3, deg + 4 * 50000, agg3, E);
    }

    {
        dim3 gP((MP + 63) / 64, 2), gA((MA + 63) / 64, 2);
        gemm_rowscale<<<gP, 256>>>(agg1, W1, deg + 1 * 50000, z1, MP);
        gemm_rowscale<<<gP, 256>>>(agg2, W2, deg + 3 * 50000, z2, MP);
        gemm_rowscale<<<gA, 256>>>(agg3, W3, deg + 5 * 50000, z3, MA);
    }

    {
        dim3 gP((MP + 63) / 64, 2);
        att_score_kernel<<<gP, 256>>>(z1, attW, attb, attq, wsum + 0, MP);
        att_score_kernel<<<gP, 256>>>(z2, attW, attb, attq, wsum + 1, MP);
    }

    stats_paper_kernel<<<(MP + 255) / 256, 128>>>(z1, z2, MP);
    stats_author_kernel<<<(MA + 255) / 256, 128>>>(z3, MA);

    finalize_kernel<<<1, 128>>>(gamma, betaBN, MP, MA);

    out_paper_kernel<<<(MP * 32 + 255) / 256, 256>>>(z1, z2, out, MP);
    out_author_kernel<<<(MA * 32 + 255) / 256, 256>>>(z3, out + (size_t)MP * Dv, MA);
}